// round 1
// baseline (speedup 1.0000x reference)
#include <cuda_runtime.h>
#include <math.h>

#define NN 1024
#define DD 64
#define DPP 32

// ---------------- scratch (device globals; re-initialized each launch) -----
__device__ float    g_dH[NN * NN];        // 4 MB pairwise ||XH_i/s - XH_j/s||
__device__ float    g_dP[NN * NN];        // 4 MB pairwise ||XP_i - XP_j||
__device__ unsigned g_mask [NN * 32];     // row-major top-K bitset (fully overwritten)
__device__ unsigned g_maskT[NN * 32];     // transposed bitset (atomicOr -> needs zeroing)
__device__ float    g_x[NN * DD];         // XX @ weight
__device__ float    g_y[NN * DD];         // x @ psi_w^T
__device__ int      g_c[NN];              // degree c[j] = sum_i A[i,j]
__device__ int      g_diag[NN];           // A[j,j]
__device__ unsigned g_mnH, g_mxH, g_mnP, g_mxP;  // float bits (all dists >= 0)
__device__ float    g_mu[DD], g_istd[DD];

// ---------------- 1. init: reset atomics + transposed mask ----------------
__global__ void k_init() {
    int t = blockIdx.x * blockDim.x + threadIdx.x;
    int stride = gridDim.x * blockDim.x;
    for (int i = t; i < NN * 32; i += stride) g_maskT[i] = 0u;
    if (t == 0) {
        g_mnH = 0x7F800000u; g_mxH = 0u;   // +inf / 0 bits; nonneg floats are uint-ordered
        g_mnP = 0x7F800000u; g_mxP = 0u;
    }
}

// ---------------- 2. pairwise distances + global min/max ------------------
__global__ void k_dist(const float* __restrict__ XH, const float* __restrict__ XP) {
    __shared__ float sHi[32][65], sHj[32][65];
    __shared__ float sPi[32][33], sPj[32][33];
    int t  = threadIdx.x;
    int i0 = blockIdx.y * 32, j0 = blockIdx.x * 32;
    const float sig = (float)(0.1 + 2.220446049250313e-16);  // sigma + float64 eps

    for (int idx = t; idx < 32 * 64; idx += 256) {
        int r = idx >> 6, d = idx & 63;
        sHi[r][d] = XH[(i0 + r) * 64 + d] / sig;
        sHj[r][d] = XH[(j0 + r) * 64 + d] / sig;
    }
    for (int idx = t; idx < 32 * 32; idx += 256) {
        int r = idx >> 5, p = idx & 31;
        sPi[r][p] = XP[(i0 + r) * 32 + p];
        sPj[r][p] = XP[(j0 + r) * 32 + p];
    }
    __syncthreads();

    int tx = t & 31, ty = t >> 5;
    unsigned lmnH = 0x7F800000u, lmxH = 0u, lmnP = 0x7F800000u, lmxP = 0u;
    #pragma unroll
    for (int r = 0; r < 4; ++r) {
        int il = ty * 4 + r;
        float sh = 0.f;
        #pragma unroll
        for (int d = 0; d < 64; ++d) { float df = sHi[il][d] - sHj[tx][d]; sh += df * df; }
        float dh = sqrtf(sh);
        float sp = 0.f;
        #pragma unroll
        for (int p = 0; p < 32; ++p) { float df = sPi[il][p] - sPj[tx][p]; sp += df * df; }
        float dp = sqrtf(sp);
        g_dH[(i0 + il) * NN + j0 + tx] = dh;
        g_dP[(i0 + il) * NN + j0 + tx] = dp;
        unsigned bh = __float_as_uint(dh), bp = __float_as_uint(dp);
        lmnH = min(lmnH, bh); lmxH = max(lmxH, bh);
        lmnP = min(lmnP, bp); lmxP = max(lmxP, bp);
    }
    lmnH = __reduce_min_sync(0xffffffffu, lmnH);
    lmxH = __reduce_max_sync(0xffffffffu, lmxH);
    lmnP = __reduce_min_sync(0xffffffffu, lmnP);
    lmxP = __reduce_max_sync(0xffffffffu, lmxP);
    if ((t & 31) == 0) {
        atomicMin(&g_mnH, lmnH); atomicMax(&g_mxH, lmxH);
        atomicMin(&g_mnP, lmnP); atomicMax(&g_mxP, lmxP);
    }
}

// ---------------- 3. per-row WW + exact top-K (ties -> lowest index) ------
__global__ void k_topk(const int* __restrict__ Kp) {
    __shared__ float    sww[NN];
    __shared__ float    sv[256];
    __shared__ int      si[256];
    __shared__ unsigned smrow[32];
    int i = blockIdx.x, t = threadIdx.x;

    float mnH = __uint_as_float(g_mnH), mxH = __uint_as_float(g_mxH);
    float mnP = __uint_as_float(g_mnP), mxP = __uint_as_float(g_mxP);
    float invH = 0.5f / (mxH - mnH);   // exp(-(q)/2)
    float invP = 1.0f / (mxP - mnP);   // exp(-(q))

    if (t < 32) smrow[t] = 0u;
    for (int j = t; j < NN; j += 256) {
        float wh = expf(-(g_dH[i * NN + j] - mnH) * invH);
        float wl = expf(-(g_dP[i * NN + j] - mnP) * invP);
        sww[j] = wh + 0.2f * wl;
    }
    __syncthreads();

    int K = Kp ? Kp[0] : 16;
    if (K < 1) K = 1; if (K > 64) K = 64;

    for (int it = 0; it < K; ++it) {
        float bv = -INFINITY; int bi = NN;
        for (int j = t; j < NN; j += 256) {         // strict > keeps lowest j in-thread
            float v = sww[j];
            if (v > bv) { bv = v; bi = j; }
        }
        sv[t] = bv; si[t] = bi;
        __syncthreads();
        for (int s = 128; s > 0; s >>= 1) {
            if (t < s) {
                if (sv[t + s] > sv[t] || (sv[t + s] == sv[t] && si[t + s] < si[t])) {
                    sv[t] = sv[t + s]; si[t] = si[t + s];
                }
            }
            __syncthreads();
        }
        if (t == 0) {
            int j = si[0];
            sww[j] = -INFINITY;
            smrow[j >> 5] |= 1u << (j & 31);
            atomicOr(&g_maskT[j * 32 + (i >> 5)], 1u << (i & 31));
        }
        __syncthreads();
    }
    if (t < 32) g_mask[i * 32 + t] = smrow[t];
}

// ---------------- 4. x = XX@W ; y = x@psi_w^T (fused, 4 rows/block) -------
__global__ void k_xy(const float* __restrict__ XX, const float* __restrict__ W,
                     const float* __restrict__ PW) {
    __shared__ float sxx[4][64], sx[4][64];
    int t = threadIdx.x;
    int r = t >> 6, d = t & 63;
    int row = blockIdx.x * 4 + r;
    sxx[r][d] = XX[row * 64 + d];
    __syncthreads();
    float acc = 0.f;
    #pragma unroll
    for (int k = 0; k < 64; ++k) acc += sxx[r][k] * W[k * 64 + d];
    sx[r][d] = acc;
    g_x[row * 64 + d] = acc;
    __syncthreads();
    float acc2 = 0.f;
    #pragma unroll
    for (int k = 0; k < 64; ++k) acc2 += sx[r][k] * PW[d * 64 + k];
    g_y[row * 64 + d] = acc2;
}

// ---------------- 5. degrees + diagonal of A = mask | mask^T --------------
__global__ void k_deg() {
    int j = blockIdx.x * blockDim.x + threadIdx.x;
    if (j >= NN) return;
    int c = 0; unsigned diagw = 0;
    #pragma unroll
    for (int w = 0; w < 32; ++w) {
        unsigned m = g_mask[j * 32 + w] | g_maskT[j * 32 + w];
        c += __popc(m);
        if (w == (j >> 5)) diagw = m;
    }
    g_c[j] = c;
    g_diag[j] = (int)((diagw >> (j & 31)) & 1u);
}

// ---------------- 6. closed-form BatchNorm stats (one block per d) --------
__global__ void k_bn(const float* __restrict__ psi_b) {
    int d = blockIdx.x, t = threadIdx.x;
    float b = psi_b[d];
    float s1 = 0.f, s2 = 0.f;
    for (int j = t; j < NN; j += 256) {
        float yv = g_y[j * DD + d];
        float c  = (float)g_c[j];
        s1 += yv * ((float)NN + c);
        float h1 = yv + b, h2 = 2.f * yv + b;
        s2 += ((float)NN - c) * h1 * h1 + c * h2 * h2;
    }
    __shared__ float ss1[256], ss2[256];
    ss1[t] = s1; ss2[t] = s2;
    __syncthreads();
    for (int s = 128; s > 0; s >>= 1) {
        if (t < s) { ss1[t] += ss1[t + s]; ss2[t] += ss2[t + s]; }
        __syncthreads();
    }
    if (t == 0) {
        const float invN2 = 1.0f / ((float)NN * (float)NN);
        float mu  = b + ss1[0] * invN2;
        float var = ss2[0] * invN2 - mu * mu;
        g_mu[d]   = mu;
        g_istd[d] = rsqrtf(var + 1e-5f);
    }
}

// ---------------- 7. final output (both out segments) ---------------------
__global__ void k_out(const float* __restrict__ psi_b, const float* __restrict__ gamma,
                      const float* __restrict__ beta, const float* __restrict__ bias,
                      float* __restrict__ out) {
    int idx = blockIdx.x * 256 + threadIdx.x;   // 65536 total
    int j = idx >> 6, d = idx & 63;
    float yv = g_y[idx], xv = g_x[idx];
    float z = (2.f * yv + psi_b[d] - g_mu[d]) * g_istd[d] * gamma[d] + beta[d];
    float s = 1.0f / (1.0f + expf(-z));
    float dg = (float)g_diag[j], c = (float)g_c[j];
    float val = xv * (dg + (c - dg) * s) + bias[d];
    out[idx] = val;                               // out[:, :DH] segment
    out[NN * DD + NN * DPP + idx] = val;          // full out segment
}

// ---------------- launch ---------------------------------------------------
extern "C" void kernel_launch(void* const* d_in, const int* in_sizes, int n_in,
                              void* d_out, int out_size) {
    // expected order: XH, XP, XX, K, weight, bias, psi_w, psi_b, gamma, beta
    int iXH = 0, iXP = 1, iXX = 2, iK = 3, iW = 4, iB = 5, iPW = 6, iPB = 7, iG = 8, iBe = 9;
    if (n_in == 9) {  // K dropped as a scalar
        iK = -1; iW = 3; iB = 4; iPW = 5; iPB = 6; iG = 7; iBe = 8;
    }
    const float* XH  = (const float*)d_in[iXH];
    const float* XP  = (const float*)d_in[iXP];
    const float* XX  = (const float*)d_in[iXX];
    const int*   Kp  = (iK >= 0) ? (const int*)d_in[iK] : nullptr;
    const float* W   = (const float*)d_in[iW];
    const float* B   = (const float*)d_in[iB];
    const float* PW  = (const float*)d_in[iPW];
    const float* PB  = (const float*)d_in[iPB];
    const float* G   = (const float*)d_in[iG];
    const float* Be  = (const float*)d_in[iBe];
    float* out = (float*)d_out;

    k_init<<<32, 256>>>();
    k_dist<<<dim3(32, 32), 256>>>(XH, XP);
    k_topk<<<NN, 256>>>(Kp);
    k_xy<<<NN / 4, 256>>>(XX, W, PW);
    k_deg<<<4, 256>>>();
    k_bn<<<DD, 256>>>(PB);
    k_out<<<256, 256>>>(PB, G, Be, B, out);
    // middle output segment: XP passthrough
    cudaMemcpyAsync(out + NN * DD, XP, NN * DPP * sizeof(float),
                    cudaMemcpyDeviceToDevice);
    (void)in_sizes; (void)out_size;
}

// round 2
// speedup vs baseline: 1.2888x; 1.2888x over previous
#include <cuda_runtime.h>
#include <math.h>

#define NN 1024
#define DD 64
#define DPP 32

// ---------------- scratch (device globals; re-initialized each launch) -----
__device__ float    g_dH[NN * NN];        // pairwise ||XH_i/s - XH_j/s|| (upper tiles), then WW (full)
__device__ float    g_dP[NN * NN];        // pairwise ||XP_i - XP_j|| (upper tiles)
__device__ unsigned g_mask [NN * 32];     // row-major top-K bitset (fully overwritten)
__device__ unsigned g_maskT[NN * 32];     // transposed bitset (atomicOr -> needs zeroing)
__device__ float    g_x[NN * DD];         // XX @ weight
__device__ float    g_y[NN * DD];         // x @ psi_w^T
__device__ int      g_c[NN];              // degree c[j] = sum_i A[i,j]
__device__ int      g_diag[NN];           // A[j,j]
__device__ unsigned g_mxH, g_mxP;         // float bits (dists >= 0; min is exactly 0 = diagonal)
__device__ float    g_mu[DD], g_istd[DD];

// ---------------- 1. init: reset atomics + transposed mask ----------------
__global__ void k_init() {
    int t = blockIdx.x * blockDim.x + threadIdx.x;
    int stride = gridDim.x * blockDim.x;
    for (int i = t; i < NN * 32; i += stride) g_maskT[i] = 0u;
    if (t == 0) { g_mxH = 0u; g_mxP = 0u; }
}

// ---------------- 2. pairwise distances (upper-triangle tiles) + max ------
__global__ void k_dist(const float* __restrict__ XH, const float* __restrict__ XP) {
    if ((int)blockIdx.x < (int)blockIdx.y) return;   // j-tile >= i-tile only
    __shared__ float sHi[32][65], sHj[32][65];
    __shared__ float sPi[32][33], sPj[32][33];
    int t  = threadIdx.x;
    int i0 = blockIdx.y * 32, j0 = blockIdx.x * 32;
    const float sig = (float)(0.1 + 2.220446049250313e-16);  // sigma + float64 eps

    for (int idx = t; idx < 32 * 64; idx += 256) {
        int r = idx >> 6, d = idx & 63;
        sHi[r][d] = XH[(i0 + r) * 64 + d] / sig;
        sHj[r][d] = XH[(j0 + r) * 64 + d] / sig;
    }
    for (int idx = t; idx < 32 * 32; idx += 256) {
        int r = idx >> 5, p = idx & 31;
        sPi[r][p] = XP[(i0 + r) * 32 + p];
        sPj[r][p] = XP[(j0 + r) * 32 + p];
    }
    __syncthreads();

    int tx = t & 31, ty = t >> 5;
    unsigned lmxH = 0u, lmxP = 0u;
    #pragma unroll
    for (int r = 0; r < 4; ++r) {
        int il = ty * 4 + r;
        float sh = 0.f;
        #pragma unroll
        for (int d = 0; d < 64; ++d) { float df = sHi[il][d] - sHj[tx][d]; sh += df * df; }
        float dh = sqrtf(sh);
        float sp = 0.f;
        #pragma unroll
        for (int p = 0; p < 32; ++p) { float df = sPi[il][p] - sPj[tx][p]; sp += df * df; }
        float dp = sqrtf(sp);
        g_dH[(i0 + il) * NN + j0 + tx] = dh;
        g_dP[(i0 + il) * NN + j0 + tx] = dp;
        lmxH = max(lmxH, __float_as_uint(dh));
        lmxP = max(lmxP, __float_as_uint(dp));
    }
    lmxH = __reduce_max_sync(0xffffffffu, lmxH);
    lmxP = __reduce_max_sync(0xffffffffu, lmxP);
    if ((t & 31) == 0) { atomicMax(&g_mxH, lmxH); atomicMax(&g_mxP, lmxP); }
}

// ---------------- 3. WW = exp + 0.2*exp (upper tiles, mirror write) -------
__global__ void k_ww() {
    int bx = blockIdx.x, by = blockIdx.y;
    if (bx < by) return;
    int t = threadIdx.x;
    int i0 = by * 32, j0 = bx * 32;
    float invH = 0.5f / __uint_as_float(g_mxH);   // min is exactly 0
    float invP = 1.0f / __uint_as_float(g_mxP);
    #pragma unroll
    for (int s = 0; s < 4; ++s) {
        int idx = t + 256 * s;
        int i = i0 + (idx >> 5), j = j0 + (idx & 31);
        if (bx == by && j < i) continue;          // diagonal tile: upper half only (avoid RAW race)
        float dh = g_dH[i * NN + j];
        float dp = g_dP[i * NN + j];
        float ww = expf(-dh * invH) + 0.2f * expf(-dp * invP);
        g_dH[i * NN + j] = ww;                    // in-place: becomes the WW matrix
        g_dH[j * NN + i] = ww;                    // mirror (symmetric)
    }
}

// ---------------- 4. exact top-K via warp selection (ties -> lowest j) ----
__device__ __forceinline__ unsigned long long warp_max_ull(unsigned long long m) {
    #pragma unroll
    for (int o = 16; o > 0; o >>= 1) {
        unsigned long long other = __shfl_xor_sync(0xffffffffu, m, o);
        if (other > m) m = other;
    }
    return m;
}

__global__ void k_topk(const int* __restrict__ Kp) {
    __shared__ unsigned long long skey[8 * 64];
    __shared__ unsigned long long ssel[64];
    __shared__ unsigned smrow[32];
    int i = blockIdx.x, t = threadIdx.x, lane = t & 31, w = t >> 5;

    int K = Kp ? Kp[0] : 16;
    if (K < 1) K = 1; if (K > 64) K = 64;
    if (t < 32) smrow[t] = 0u;

    // load 128 WW values per warp as order-preserving keys (WW > 0 -> bits uint-ordered)
    unsigned long long key[4];
    #pragma unroll
    for (int s = 0; s < 4; ++s) {
        int j = w * 128 + s * 32 + lane;
        float v = g_dH[i * NN + j];
        key[s] = ((unsigned long long)__float_as_uint(v) << 32) | (unsigned)(NN - 1 - j);
    }
    // per-warp local top-K (keys unique: index embedded)
    for (int it = 0; it < K; ++it) {
        unsigned long long m = key[0];
        if (key[1] > m) m = key[1];
        if (key[2] > m) m = key[2];
        if (key[3] > m) m = key[3];
        m = warp_max_ull(m);
        #pragma unroll
        for (int s = 0; s < 4; ++s) if (key[s] == m) key[s] = 0ULL;
        if (lane == 0) skey[w * 64 + it] = m;
    }
    __syncthreads();

    // warp 0 merges 8*K candidates
    if (w == 0) {
        int cnt = 8 * K;
        int nseg = (cnt + 31) >> 5;               // <= 16
        unsigned long long mk[16];
        for (int s = 0; s < nseg; ++s) {
            int c = s * 32 + lane;
            mk[s] = (c < cnt) ? skey[(c / K) * 64 + (c % K)] : 0ULL;
        }
        for (int it = 0; it < K; ++it) {
            unsigned long long m = 0ULL;
            for (int s = 0; s < nseg; ++s) if (mk[s] > m) m = mk[s];
            m = warp_max_ull(m);
            for (int s = 0; s < nseg; ++s) if (mk[s] == m) mk[s] = 0ULL;
            if (lane == 0) ssel[it] = m;
        }
    }
    __syncthreads();

    if (t < K) {
        int j = NN - 1 - (int)(ssel[t] & 0xFFFFFFFFu);
        atomicOr(&smrow[j >> 5], 1u << (j & 31));
        atomicOr(&g_maskT[j * 32 + (i >> 5)], 1u << (i & 31));
    }
    __syncthreads();
    if (t < 32) g_mask[i * 32 + t] = smrow[t];
}

// ---------------- 5. x = XX@W ; y = x@psi_w^T (shared-staged weights) -----
__global__ void k_xy(const float* __restrict__ XX, const float* __restrict__ W,
                     const float* __restrict__ PW) {
    __shared__ float sW[64 * 64];     // sW[k*64+d]
    __shared__ float sPW[64 * 65];    // sPW[d*65+k] (padded)
    __shared__ float sXX[16 * 64];
    __shared__ float sx[16 * 64];
    int t = threadIdx.x;
    int row0 = blockIdx.x * 16;

    for (int idx = t; idx < 4096; idx += 256) sW[idx] = W[idx];
    for (int idx = t; idx < 4096; idx += 256) {
        int d = idx >> 6, k = idx & 63;
        sPW[d * 65 + k] = PW[idx];
    }
    for (int idx = t; idx < 1024; idx += 256) sXX[idx] = XX[row0 * 64 + idx];
    __syncthreads();

    int d = t & 63, rg = t >> 6;      // 4 row-groups x 4 rows
    float acc[4] = {0.f, 0.f, 0.f, 0.f};
    #pragma unroll
    for (int k = 0; k < 64; ++k) {
        float wv = sW[k * 64 + d];
        #pragma unroll
        for (int rr = 0; rr < 4; ++rr) acc[rr] += sXX[(rg * 4 + rr) * 64 + k] * wv;
    }
    #pragma unroll
    for (int rr = 0; rr < 4; ++rr) {
        sx[(rg * 4 + rr) * 64 + d] = acc[rr];
        g_x[(row0 + rg * 4 + rr) * 64 + d] = acc[rr];
    }
    __syncthreads();

    float a2[4] = {0.f, 0.f, 0.f, 0.f};
    #pragma unroll
    for (int k = 0; k < 64; ++k) {
        float pw = sPW[d * 65 + k];
        #pragma unroll
        for (int rr = 0; rr < 4; ++rr) a2[rr] += sx[(rg * 4 + rr) * 64 + k] * pw;
    }
    #pragma unroll
    for (int rr = 0; rr < 4; ++rr) g_y[(row0 + rg * 4 + rr) * 64 + d] = a2[rr];
}

// ---------------- 6. degrees + diagonal of A = mask | mask^T --------------
__global__ void k_deg() {
    int j = blockIdx.x * blockDim.x + threadIdx.x;
    if (j >= NN) return;
    int c = 0; unsigned diagw = 0;
    #pragma unroll
    for (int w = 0; w < 32; ++w) {
        unsigned m = g_mask[j * 32 + w] | g_maskT[j * 32 + w];
        c += __popc(m);
        if (w == (j >> 5)) diagw = m;
    }
    g_c[j] = c;
    g_diag[j] = (int)((diagw >> (j & 31)) & 1u);
}

// ---------------- 7. closed-form BatchNorm stats (one block per d) --------
__global__ void k_bn(const float* __restrict__ psi_b) {
    int d = blockIdx.x, t = threadIdx.x;
    float b = psi_b[d];
    float s1 = 0.f, s2 = 0.f;
    for (int j = t; j < NN; j += 256) {
        float yv = g_y[j * DD + d];
        float c  = (float)g_c[j];
        s1 += yv * ((float)NN + c);
        float h1 = yv + b, h2 = 2.f * yv + b;
        s2 += ((float)NN - c) * h1 * h1 + c * h2 * h2;
    }
    __shared__ float ss1[256], ss2[256];
    ss1[t] = s1; ss2[t] = s2;
    __syncthreads();
    for (int s = 128; s > 0; s >>= 1) {
        if (t < s) { ss1[t] += ss1[t + s]; ss2[t] += ss2[t + s]; }
        __syncthreads();
    }
    if (t == 0) {
        const float invN2 = 1.0f / ((float)NN * (float)NN);
        float mu  = b + ss1[0] * invN2;
        float var = ss2[0] * invN2 - mu * mu;
        g_mu[d]   = mu;
        g_istd[d] = rsqrtf(var + 1e-5f);
    }
}

// ---------------- 8. final output (both out segments) ---------------------
__global__ void k_out(const float* __restrict__ psi_b, const float* __restrict__ gamma,
                      const float* __restrict__ beta, const float* __restrict__ bias,
                      float* __restrict__ out) {
    int idx = blockIdx.x * 256 + threadIdx.x;   // 65536 total
    int j = idx >> 6, d = idx & 63;
    float yv = g_y[idx], xv = g_x[idx];
    float z = (2.f * yv + psi_b[d] - g_mu[d]) * g_istd[d] * gamma[d] + beta[d];
    float s = 1.0f / (1.0f + expf(-z));
    float dg = (float)g_diag[j], c = (float)g_c[j];
    float val = xv * (dg + (c - dg) * s) + bias[d];
    out[idx] = val;                               // out[:, :DH] segment
    out[NN * DD + NN * DPP + idx] = val;          // full out segment
}

// ---------------- launch ---------------------------------------------------
extern "C" void kernel_launch(void* const* d_in, const int* in_sizes, int n_in,
                              void* d_out, int out_size) {
    // expected order: XH, XP, XX, K, weight, bias, psi_w, psi_b, gamma, beta
    int iXH = 0, iXP = 1, iXX = 2, iK = 3, iW = 4, iB = 5, iPW = 6, iPB = 7, iG = 8, iBe = 9;
    if (n_in == 9) {  // K dropped as a scalar
        iK = -1; iW = 3; iB = 4; iPW = 5; iPB = 6; iG = 7; iBe = 8;
    }
    const float* XH  = (const float*)d_in[iXH];
    const float* XP  = (const float*)d_in[iXP];
    const float* XX  = (const float*)d_in[iXX];
    const int*   Kp  = (iK >= 0) ? (const int*)d_in[iK] : nullptr;
    const float* W   = (const float*)d_in[iW];
    const float* B   = (const float*)d_in[iB];
    const float* PW  = (const float*)d_in[iPW];
    const float* PB  = (const float*)d_in[iPB];
    const float* G   = (const float*)d_in[iG];
    const float* Be  = (const float*)d_in[iBe];
    float* out = (float*)d_out;

    k_init<<<32, 256>>>();
    k_xy<<<64, 256>>>(XX, W, PW);               // independent of adjacency path
    k_dist<<<dim3(32, 32), 256>>>(XH, XP);
    k_ww<<<dim3(32, 32), 256>>>();
    k_topk<<<NN, 256>>>(Kp);
    k_deg<<<4, 256>>>();
    k_bn<<<DD, 256>>>(PB);
    k_out<<<256, 256>>>(PB, G, Be, B, out);
    // middle output segment: XP passthrough
    cudaMemcpyAsync(out + NN * DD, XP, NN * DPP * sizeof(float),
                    cudaMemcpyDeviceToDevice);
    (void)in_sizes; (void)out_size;
}

// round 3
// speedup vs baseline: 1.7167x; 1.3320x over previous
#include <cuda_runtime.h>
#include <math.h>

#define NN 1024
#define DD 64
#define DPP 32

// ---------------- scratch (device globals) ---------------------------------
__device__ float2   g_d2[NN * NN];        // 8 MB: (dH, dP) pairwise, full mirrored
__device__ unsigned g_mask [NN * 32];     // row-major top-K bitset (fully overwritten)
__device__ unsigned g_maskT[NN * 32];     // transposed bitset (atomicOr; zeroed in k_xy)
__device__ float    g_x[NN * DD];         // XX @ weight
__device__ float    g_y[NN * DD];         // x @ psi_w^T
__device__ int      g_c[NN];              // degree c[j]
__device__ int      g_diag[NN];           // A[j,j]
__device__ unsigned g_mxH, g_mxP;         // float bits (dists >= 0; min is exactly 0)
__device__ float    g_mu[DD], g_istd[DD];

// ---------------- 1. x = XX@W ; y = x@psi_w^T  (+ init of maskT / maxes) ---
__global__ void k_xy(const float* __restrict__ XX, const float* __restrict__ W,
                     const float* __restrict__ PW) {
    // init section (runs before k_dist/k_topk by stream order)
    int gt = blockIdx.x * 256 + threadIdx.x;     // 16384 threads
    g_maskT[gt * 2]     = 0u;
    g_maskT[gt * 2 + 1] = 0u;
    if (gt == 0) { g_mxH = 0u; g_mxP = 0u; }

    __shared__ float sW[64 * 64];     // sW[k*64+d]
    __shared__ float sPW[64 * 65];    // sPW[d*65+k] (padded)
    __shared__ float sXX[16 * 64];
    __shared__ float sx[16 * 64];
    int t = threadIdx.x;
    int row0 = blockIdx.x * 16;

    for (int idx = t; idx < 4096; idx += 256) sW[idx] = W[idx];
    for (int idx = t; idx < 4096; idx += 256) {
        int d = idx >> 6, k = idx & 63;
        sPW[d * 65 + k] = PW[idx];
    }
    for (int idx = t; idx < 1024; idx += 256) sXX[idx] = XX[row0 * 64 + idx];
    __syncthreads();

    int d = t & 63, rg = t >> 6;
    float acc[4] = {0.f, 0.f, 0.f, 0.f};
    #pragma unroll
    for (int k = 0; k < 64; ++k) {
        float wv = sW[k * 64 + d];
        #pragma unroll
        for (int rr = 0; rr < 4; ++rr) acc[rr] += sXX[(rg * 4 + rr) * 64 + k] * wv;
    }
    #pragma unroll
    for (int rr = 0; rr < 4; ++rr) {
        sx[(rg * 4 + rr) * 64 + d] = acc[rr];
        g_x[(row0 + rg * 4 + rr) * 64 + d] = acc[rr];
    }
    __syncthreads();

    float a2[4] = {0.f, 0.f, 0.f, 0.f};
    #pragma unroll
    for (int k = 0; k < 64; ++k) {
        float pw = sPW[d * 65 + k];
        #pragma unroll
        for (int rr = 0; rr < 4; ++rr) a2[rr] += sx[(rg * 4 + rr) * 64 + k] * pw;
    }
    #pragma unroll
    for (int rr = 0; rr < 4; ++rr) g_y[(row0 + rg * 4 + rr) * 64 + d] = a2[rr];
}

// ---------------- 2. distances: 64x64 tiles, 4x4 reg blocking, mirrored ----
__global__ void k_dist(const float* __restrict__ XH, const float* __restrict__ XP) {
    __shared__ float pool[64 * 66 * 2];   // 8448 floats = 33 KB, phase-aliased
    int t = threadIdx.x;

    // decode upper-triangle tile index (136 blocks over 16x16 tiles, by<=bx)
    int by = 0, rem = blockIdx.x;
    while (rem >= 16 - by) { rem -= 16 - by; ++by; }
    int bx = by + rem;
    int i0 = by * 64, j0 = bx * 64;
    int tx = t & 15, ty = t >> 4;
    const float sig = (float)(0.1 + 2.220446049250313e-16);  // sigma + float64 eps

    // phase 1: H features (64 dims)
    float (*sA)[65] = (float(*)[65])pool;
    float (*sB)[65] = (float(*)[65])(pool + 64 * 65);
    for (int idx = t; idx < 4096; idx += 256) {
        int r = idx >> 6, d = idx & 63;
        sA[r][d] = XH[(i0 + r) * 64 + d] / sig;
        sB[r][d] = XH[(j0 + r) * 64 + d] / sig;
    }
    __syncthreads();

    float accH[4][4];
    #pragma unroll
    for (int a = 0; a < 4; ++a)
        #pragma unroll
        for (int b = 0; b < 4; ++b) accH[a][b] = 0.f;
    #pragma unroll 8
    for (int d = 0; d < 64; ++d) {
        float rI[4], rJ[4];
        #pragma unroll
        for (int a = 0; a < 4; ++a) rI[a] = sA[ty + 16 * a][d];
        #pragma unroll
        for (int b = 0; b < 4; ++b) rJ[b] = sB[tx + 16 * b][d];
        #pragma unroll
        for (int a = 0; a < 4; ++a)
            #pragma unroll
            for (int b = 0; b < 4; ++b) {
                float df = rI[a] - rJ[b];
                accH[a][b] += df * df;
            }
    }
    __syncthreads();

    // phase 2: P features (32 dims), reuse pool
    float (*pA)[33] = (float(*)[33])pool;
    float (*pB)[33] = (float(*)[33])(pool + 64 * 33);
    for (int idx = t; idx < 2048; idx += 256) {
        int r = idx >> 5, p = idx & 31;
        pA[r][p] = XP[(i0 + r) * 32 + p];
        pB[r][p] = XP[(j0 + r) * 32 + p];
    }
    __syncthreads();

    float accP[4][4];
    #pragma unroll
    for (int a = 0; a < 4; ++a)
        #pragma unroll
        for (int b = 0; b < 4; ++b) accP[a][b] = 0.f;
    #pragma unroll 8
    for (int p = 0; p < 32; ++p) {
        float rI[4], rJ[4];
        #pragma unroll
        for (int a = 0; a < 4; ++a) rI[a] = pA[ty + 16 * a][p];
        #pragma unroll
        for (int b = 0; b < 4; ++b) rJ[b] = pB[tx + 16 * b][p];
        #pragma unroll
        for (int a = 0; a < 4; ++a)
            #pragma unroll
            for (int b = 0; b < 4; ++b) {
                float df = rI[a] - rJ[b];
                accP[a][b] += df * df;
            }
    }

    // phase 3: sqrt, straight write, max tracking
    float2 res[4][4];
    unsigned lmH = 0u, lmP = 0u;
    #pragma unroll
    for (int a = 0; a < 4; ++a)
        #pragma unroll
        for (int b = 0; b < 4; ++b) {
            float dh = sqrtf(accH[a][b]);
            float dp = sqrtf(accP[a][b]);
            res[a][b] = make_float2(dh, dp);
            lmH = max(lmH, __float_as_uint(dh));
            lmP = max(lmP, __float_as_uint(dp));
            g_d2[(i0 + ty + 16 * a) * NN + (j0 + tx + 16 * b)] = res[a][b];
        }
    lmH = __reduce_max_sync(0xffffffffu, lmH);
    lmP = __reduce_max_sync(0xffffffffu, lmP);
    if ((t & 31) == 0) { atomicMax(&g_mxH, lmH); atomicMax(&g_mxP, lmP); }

    // phase 4: mirror tile via shared transpose (coalesced both ways)
    if (bx != by) {
        __syncthreads();                              // done reading P smem
        float2 (*st)[66] = (float2(*)[66])pool;
        #pragma unroll
        for (int a = 0; a < 4; ++a)
            #pragma unroll
            for (int b = 0; b < 4; ++b)
                st[tx + 16 * b][ty + 16 * a] = res[a][b];
        __syncthreads();
        for (int idx = t; idx < 4096; idx += 256) {
            int r = idx >> 6, c = idx & 63;
            g_d2[(j0 + r) * NN + (i0 + c)] = st[r][c];
        }
    }
}

// ---------------- 3. fused WW + exact top-K (one warp per row) -------------
__global__ void k_topk(const int* __restrict__ Kp) {
    int t = threadIdx.x, lane = t & 31, w = t >> 5;
    int i = blockIdx.x * 8 + w;

    float mxH = __uint_as_float(g_mxH), mxP = __uint_as_float(g_mxP);
    float invH = 0.5f / mxH;              // min is exactly 0 (diagonal)
    float invP = 1.0f / mxP;

    // load row, compute WW keys (WW > 0 -> float bits are uint-ordered)
    unsigned key[32];
    #pragma unroll
    for (int s = 0; s < 32; ++s) {
        float2 dv = g_d2[i * NN + s * 32 + lane];
        float ww = expf(-dv.x * invH) + 0.2f * expf(-dv.y * invP);
        key[s] = __float_as_uint(ww);
    }

    int K = Kp ? Kp[0] : 16;
    if (K < 1) K = 1; if (K > NN) K = NN;

    unsigned mrow = 0u;                   // lane L accumulates mask word L
    for (int it = 0; it < K; ++it) {
        unsigned lm = 0u;
        #pragma unroll
        for (int s = 0; s < 32; ++s) lm = max(lm, key[s]);
        unsigned wm = __reduce_max_sync(0xffffffffu, lm);
        // lowest j holding wm (exact jax tie semantics)
        int jc = 0x7fffffff;
        #pragma unroll
        for (int s = 0; s < 32; ++s)
            if (key[s] == wm && s * 32 + lane < jc) jc = s * 32 + lane;
        int jmin = __reduce_min_sync(0xffffffffu, (unsigned)jc);
        // remove from owner lane; record bit
        if (lane == (jmin & 31)) key[jmin >> 5] = 0u;
        if (lane == (jmin >> 5)) mrow |= 1u << (jmin & 31);
        if (lane == 0)
            atomicOr(&g_maskT[jmin * 32 + (i >> 5)], 1u << (i & 31));
    }
    g_mask[i * 32 + lane] = mrow;
}

// ---------------- 4. degrees + diagonal of A = mask | mask^T ---------------
__global__ void k_deg() {
    int j = blockIdx.x * blockDim.x + threadIdx.x;
    if (j >= NN) return;
    int c = 0; unsigned diagw = 0;
    #pragma unroll
    for (int w = 0; w < 32; ++w) {
        unsigned m = g_mask[j * 32 + w] | g_maskT[j * 32 + w];
        c += __popc(m);
        if (w == (j >> 5)) diagw = m;
    }
    g_c[j] = c;
    g_diag[j] = (int)((diagw >> (j & 31)) & 1u);
}

// ---------------- 5. closed-form BatchNorm stats (one block per d) ---------
__global__ void k_bn(const float* __restrict__ psi_b) {
    int d = blockIdx.x, t = threadIdx.x;
    float b = psi_b[d];
    float s1 = 0.f, s2 = 0.f;
    for (int j = t; j < NN; j += 256) {
        float yv = g_y[j * DD + d];
        float c  = (float)g_c[j];
        s1 += yv * ((float)NN + c);
        float h1 = yv + b, h2 = 2.f * yv + b;
        s2 += ((float)NN - c) * h1 * h1 + c * h2 * h2;
    }
    __shared__ float ss1[256], ss2[256];
    ss1[t] = s1; ss2[t] = s2;
    __syncthreads();
    for (int s = 128; s > 0; s >>= 1) {
        if (t < s) { ss1[t] += ss1[t + s]; ss2[t] += ss2[t + s]; }
        __syncthreads();
    }
    if (t == 0) {
        const float invN2 = 1.0f / ((float)NN * (float)NN);
        float mu  = b + ss1[0] * invN2;
        float var = ss2[0] * invN2 - mu * mu;
        g_mu[d]   = mu;
        g_istd[d] = rsqrtf(var + 1e-5f);
    }
}

// ---------------- 6. final output (all three out segments) -----------------
__global__ void k_out(const float* __restrict__ psi_b, const float* __restrict__ gamma,
                      const float* __restrict__ beta, const float* __restrict__ bias,
                      const float* __restrict__ XP, float* __restrict__ out) {
    int idx = blockIdx.x * 256 + threadIdx.x;   // 65536 total
    int j = idx >> 6, d = idx & 63;
    float yv = g_y[idx], xv = g_x[idx];
    float z = (2.f * yv + psi_b[d] - g_mu[d]) * g_istd[d] * gamma[d] + beta[d];
    float s = 1.0f / (1.0f + expf(-z));
    float dg = (float)g_diag[j], c = (float)g_c[j];
    float val = xv * (dg + (c - dg) * s) + bias[d];
    out[idx] = val;                               // out[:, :DH] segment
    out[NN * DD + NN * DPP + idx] = val;          // full out segment
    if (idx < NN * DPP) out[NN * DD + idx] = XP[idx];  // XP passthrough
}

// ---------------- launch ----------------------------------------------------
extern "C" void kernel_launch(void* const* d_in, const int* in_sizes, int n_in,
                              void* d_out, int out_size) {
    // expected order: XH, XP, XX, K, weight, bias, psi_w, psi_b, gamma, beta
    int iXH = 0, iXP = 1, iXX = 2, iK = 3, iW = 4, iB = 5, iPW = 6, iPB = 7, iG = 8, iBe = 9;
    if (n_in == 9) {  // K dropped as a scalar
        iK = -1; iW = 3; iB = 4; iPW = 5; iPB = 6; iG = 7; iBe = 8;
    }
    const float* XH  = (const float*)d_in[iXH];
    const float* XP  = (const float*)d_in[iXP];
    const float* XX  = (const float*)d_in[iXX];
    const int*   Kp  = (iK >= 0) ? (const int*)d_in[iK] : nullptr;
    const float* W   = (const float*)d_in[iW];
    const float* B   = (const float*)d_in[iB];
    const float* PW  = (const float*)d_in[iPW];
    const float* PB  = (const float*)d_in[iPB];
    const float* G   = (const float*)d_in[iG];
    const float* Be  = (const float*)d_in[iBe];
    float* out = (float*)d_out;

    k_xy  <<<64, 256>>>(XX, W, PW);       // also zeroes maskT + resets maxes
    k_dist<<<136, 256>>>(XH, XP);
    k_topk<<<128, 256>>>(Kp);
    k_deg <<<4, 256>>>();
    k_bn  <<<DD, 256>>>(PB);
    k_out <<<256, 256>>>(PB, G, Be, B, XP, out);
    (void)in_sizes; (void)out_size;
}

// round 4
// speedup vs baseline: 1.7248x; 1.0048x over previous
#include <cuda_runtime.h>
#include <math.h>

#define NN 1024
#define DD 64
#define DPP 32

// ---------------- scratch (device globals) ---------------------------------
__device__ float2   g_d2[NN * NN];        // 8 MB: (dH, dP) pairwise, full mirrored
__device__ unsigned g_mask [NN * 32];     // row-major top-K bitset (fully overwritten)
__device__ unsigned g_maskT[NN * 32];     // transposed bitset (atomicOr; zeroed in k_xy)
__device__ float    g_x[NN * DD];         // XX @ weight
__device__ float    g_y[NN * DD];         // x @ psi_w^T
__device__ int      g_c[NN];              // degree c[j]
__device__ int      g_diag[NN];           // A[j,j]
__device__ unsigned g_mxH, g_mxP;         // float bits (dists >= 0; min is exactly 0)
__device__ float    g_mu[DD], g_istd[DD];

// ---------------- 1. x = XX@W ; y = x@psi_w^T  (+ init of maskT / maxes) ---
__global__ void k_xy(const float* __restrict__ XX, const float* __restrict__ W,
                     const float* __restrict__ PW) {
    // init section (runs before k_dist/k_topk by stream order)
    int gt = blockIdx.x * 256 + threadIdx.x;     // 16384 threads
    g_maskT[gt * 2]     = 0u;
    g_maskT[gt * 2 + 1] = 0u;
    if (gt == 0) { g_mxH = 0u; g_mxP = 0u; }

    __shared__ float sW[64 * 64];     // sW[k*64+d]
    __shared__ float sPW[64 * 65];    // sPW[d*65+k] (padded)
    __shared__ float sXX[16 * 64];
    __shared__ float sx[16 * 64];
    int t = threadIdx.x;
    int row0 = blockIdx.x * 16;

    for (int idx = t; idx < 4096; idx += 256) sW[idx] = W[idx];
    for (int idx = t; idx < 4096; idx += 256) {
        int d = idx >> 6, k = idx & 63;
        sPW[d * 65 + k] = PW[idx];
    }
    for (int idx = t; idx < 1024; idx += 256) sXX[idx] = XX[row0 * 64 + idx];
    __syncthreads();

    int d = t & 63, rg = t >> 6;
    float acc[4] = {0.f, 0.f, 0.f, 0.f};
    #pragma unroll
    for (int k = 0; k < 64; ++k) {
        float wv = sW[k * 64 + d];
        #pragma unroll
        for (int rr = 0; rr < 4; ++rr) acc[rr] += sXX[(rg * 4 + rr) * 64 + k] * wv;
    }
    #pragma unroll
    for (int rr = 0; rr < 4; ++rr) {
        sx[(rg * 4 + rr) * 64 + d] = acc[rr];
        g_x[(row0 + rg * 4 + rr) * 64 + d] = acc[rr];
    }
    __syncthreads();

    float a2[4] = {0.f, 0.f, 0.f, 0.f};
    #pragma unroll
    for (int k = 0; k < 64; ++k) {
        float pw = sPW[d * 65 + k];
        #pragma unroll
        for (int rr = 0; rr < 4; ++rr) a2[rr] += sx[(rg * 4 + rr) * 64 + k] * pw;
    }
    #pragma unroll
    for (int rr = 0; rr < 4; ++rr) g_y[(row0 + rg * 4 + rr) * 64 + d] = a2[rr];
}

// ---------------- 2. distances: 64x64 tiles, 4x4 reg blocking, mirrored ----
__global__ void k_dist(const float* __restrict__ XH, const float* __restrict__ XP) {
    __shared__ float pool[64 * 66 * 2];   // 8448 floats = 33 KB, phase-aliased
    int t = threadIdx.x;

    // decode upper-triangle tile index (136 blocks over 16x16 tiles, by<=bx)
    int by = 0, rem = blockIdx.x;
    while (rem >= 16 - by) { rem -= 16 - by; ++by; }
    int bx = by + rem;
    int i0 = by * 64, j0 = bx * 64;
    int tx = t & 15, ty = t >> 4;
    const float sig = (float)(0.1 + 2.220446049250313e-16);  // sigma + float64 eps

    // phase 1: H features (64 dims)
    float (*sA)[65] = (float(*)[65])pool;
    float (*sB)[65] = (float(*)[65])(pool + 64 * 65);
    for (int idx = t; idx < 4096; idx += 256) {
        int r = idx >> 6, d = idx & 63;
        sA[r][d] = XH[(i0 + r) * 64 + d] / sig;
        sB[r][d] = XH[(j0 + r) * 64 + d] / sig;
    }
    __syncthreads();

    float accH[4][4];
    #pragma unroll
    for (int a = 0; a < 4; ++a)
        #pragma unroll
        for (int b = 0; b < 4; ++b) accH[a][b] = 0.f;
    #pragma unroll 8
    for (int d = 0; d < 64; ++d) {
        float rI[4], rJ[4];
        #pragma unroll
        for (int a = 0; a < 4; ++a) rI[a] = sA[ty + 16 * a][d];
        #pragma unroll
        for (int b = 0; b < 4; ++b) rJ[b] = sB[tx + 16 * b][d];
        #pragma unroll
        for (int a = 0; a < 4; ++a)
            #pragma unroll
            for (int b = 0; b < 4; ++b) {
                float df = rI[a] - rJ[b];
                accH[a][b] += df * df;
            }
    }
    __syncthreads();

    // phase 2: P features (32 dims), reuse pool
    float (*pA)[33] = (float(*)[33])pool;
    float (*pB)[33] = (float(*)[33])(pool + 64 * 33);
    for (int idx = t; idx < 2048; idx += 256) {
        int r = idx >> 5, p = idx & 31;
        pA[r][p] = XP[(i0 + r) * 32 + p];
        pB[r][p] = XP[(j0 + r) * 32 + p];
    }
    __syncthreads();

    float accP[4][4];
    #pragma unroll
    for (int a = 0; a < 4; ++a)
        #pragma unroll
        for (int b = 0; b < 4; ++b) accP[a][b] = 0.f;
    #pragma unroll 8
    for (int p = 0; p < 32; ++p) {
        float rI[4], rJ[4];
        #pragma unroll
        for (int a = 0; a < 4; ++a) rI[a] = pA[ty + 16 * a][p];
        #pragma unroll
        for (int b = 0; b < 4; ++b) rJ[b] = pB[tx + 16 * b][p];
        #pragma unroll
        for (int a = 0; a < 4; ++a)
            #pragma unroll
            for (int b = 0; b < 4; ++b) {
                float df = rI[a] - rJ[b];
                accP[a][b] += df * df;
            }
    }

    // phase 3: sqrt, straight write, max tracking
    float2 res[4][4];
    unsigned lmH = 0u, lmP = 0u;
    #pragma unroll
    for (int a = 0; a < 4; ++a)
        #pragma unroll
        for (int b = 0; b < 4; ++b) {
            float dh = sqrtf(accH[a][b]);
            float dp = sqrtf(accP[a][b]);
            res[a][b] = make_float2(dh, dp);
            lmH = max(lmH, __float_as_uint(dh));
            lmP = max(lmP, __float_as_uint(dp));
            g_d2[(i0 + ty + 16 * a) * NN + (j0 + tx + 16 * b)] = res[a][b];
        }
    lmH = __reduce_max_sync(0xffffffffu, lmH);
    lmP = __reduce_max_sync(0xffffffffu, lmP);
    if ((t & 31) == 0) { atomicMax(&g_mxH, lmH); atomicMax(&g_mxP, lmP); }

    // phase 4: mirror tile via shared transpose (coalesced both ways)
    if (bx != by) {
        __syncthreads();                              // done reading P smem
        float2 (*st)[66] = (float2(*)[66])pool;
        #pragma unroll
        for (int a = 0; a < 4; ++a)
            #pragma unroll
            for (int b = 0; b < 4; ++b)
                st[tx + 16 * b][ty + 16 * a] = res[a][b];
        __syncthreads();
        for (int idx = t; idx < 4096; idx += 256) {
            int r = idx >> 6, c = idx & 63;
            g_d2[(j0 + r) * NN + (i0 + c)] = st[r][c];
        }
    }
}

// ---------------- 3. fused WW + exact top-K (one warp per row) -------------
__global__ void k_topk(const int* __restrict__ Kp) {
    int t = threadIdx.x, lane = t & 31, w = t >> 5;
    int i = blockIdx.x * 8 + w;

    float mxH = __uint_as_float(g_mxH), mxP = __uint_as_float(g_mxP);
    float invH = 0.5f / mxH;              // min is exactly 0 (diagonal)
    float invP = 1.0f / mxP;

    // load row, compute WW keys (WW > 0 -> float bits are uint-ordered)
    unsigned key[32];
    #pragma unroll
    for (int s = 0; s < 32; ++s) {
        float2 dv = g_d2[i * NN + s * 32 + lane];
        float ww = expf(-dv.x * invH) + 0.2f * expf(-dv.y * invP);
        key[s] = __float_as_uint(ww);
    }

    int K = Kp ? Kp[0] : 16;
    if (K < 1) K = 1; if (K > NN) K = NN;

    unsigned mrow = 0u;                   // lane L accumulates mask word L
    for (int it = 0; it < K; ++it) {
        unsigned lm = 0u;
        #pragma unroll
        for (int s = 0; s < 32; ++s) lm = max(lm, key[s]);
        unsigned wm = __reduce_max_sync(0xffffffffu, lm);
        // lowest j holding wm (exact jax tie semantics)
        int jc = 0x7fffffff;
        #pragma unroll
        for (int s = 0; s < 32; ++s)
            if (key[s] == wm && s * 32 + lane < jc) jc = s * 32 + lane;
        int jmin = __reduce_min_sync(0xffffffffu, (unsigned)jc);
        // remove from owner lane; record bit
        if (lane == (jmin & 31)) key[jmin >> 5] = 0u;
        if (lane == (jmin >> 5)) mrow |= 1u << (jmin & 31);
        if (lane == 0)
            atomicOr(&g_maskT[jmin * 32 + (i >> 5)], 1u << (i & 31));
    }
    g_mask[i * 32 + lane] = mrow;
}

// ---------------- 4. degrees + diagonal of A = mask | mask^T ---------------
__global__ void k_deg() {
    int j = blockIdx.x * blockDim.x + threadIdx.x;
    if (j >= NN) return;
    int c = 0; unsigned diagw = 0;
    #pragma unroll
    for (int w = 0; w < 32; ++w) {
        unsigned m = g_mask[j * 32 + w] | g_maskT[j * 32 + w];
        c += __popc(m);
        if (w == (j >> 5)) diagw = m;
    }
    g_c[j] = c;
    g_diag[j] = (int)((diagw >> (j & 31)) & 1u);
}

// ---------------- 5. closed-form BatchNorm stats (one block per d) ---------
__global__ void k_bn(const float* __restrict__ psi_b) {
    int d = blockIdx.x, t = threadIdx.x;
    float b = psi_b[d];
    float s1 = 0.f, s2 = 0.f;
    for (int j = t; j < NN; j += 256) {
        float yv = g_y[j * DD + d];
        float c  = (float)g_c[j];
        s1 += yv * ((float)NN + c);
        float h1 = yv + b, h2 = 2.f * yv + b;
        s2 += ((float)NN - c) * h1 * h1 + c * h2 * h2;
    }
    __shared__ float ss1[256], ss2[256];
    ss1[t] = s1; ss2[t] = s2;
    __syncthreads();
    for (int s = 128; s > 0; s >>= 1) {
        if (t < s) { ss1[t] += ss1[t + s]; ss2[t] += ss2[t + s]; }
        __syncthreads();
    }
    if (t == 0) {
        const float invN2 = 1.0f / ((float)NN * (float)NN);
        float mu  = b + ss1[0] * invN2;
        float var = ss2[0] * invN2 - mu * mu;
        g_mu[d]   = mu;
        g_istd[d] = rsqrtf(var + 1e-5f);
    }
}

// ---------------- 6. final output (all three out segments) -----------------
__global__ void k_out(const float* __restrict__ psi_b, const float* __restrict__ gamma,
                      const float* __restrict__ beta, const float* __restrict__ bias,
                      const float* __restrict__ XP, float* __restrict__ out) {
    int idx = blockIdx.x * 256 + threadIdx.x;   // 65536 total
    int j = idx >> 6, d = idx & 63;
    float yv = g_y[idx], xv = g_x[idx];
    float z = (2.f * yv + psi_b[d] - g_mu[d]) * g_istd[d] * gamma[d] + beta[d];
    float s = 1.0f / (1.0f + expf(-z));
    float dg = (float)g_diag[j], c = (float)g_c[j];
    float val = xv * (dg + (c - dg) * s) + bias[d];
    out[idx] = val;                               // out[:, :DH] segment
    out[NN * DD + NN * DPP + idx] = val;          // full out segment
    if (idx < NN * DPP) out[NN * DD + idx] = XP[idx];  // XP passthrough
}

// ---------------- launch ----------------------------------------------------
extern "C" void kernel_launch(void* const* d_in, const int* in_sizes, int n_in,
                              void* d_out, int out_size) {
    // expected order: XH, XP, XX, K, weight, bias, psi_w, psi_b, gamma, beta
    int iXH = 0, iXP = 1, iXX = 2, iK = 3, iW = 4, iB = 5, iPW = 6, iPB = 7, iG = 8, iBe = 9;
    if (n_in == 9) {  // K dropped as a scalar
        iK = -1; iW = 3; iB = 4; iPW = 5; iPB = 6; iG = 7; iBe = 8;
    }
    const float* XH  = (const float*)d_in[iXH];
    const float* XP  = (const float*)d_in[iXP];
    const float* XX  = (const float*)d_in[iXX];
    const int*   Kp  = (iK >= 0) ? (const int*)d_in[iK] : nullptr;
    const float* W   = (const float*)d_in[iW];
    const float* B   = (const float*)d_in[iB];
    const float* PW  = (const float*)d_in[iPW];
    const float* PB  = (const float*)d_in[iPB];
    const float* G   = (const float*)d_in[iG];
    const float* Be  = (const float*)d_in[iBe];
    float* out = (float*)d_out;

    k_xy  <<<64, 256>>>(XX, W, PW);       // also zeroes maskT + resets maxes
    k_dist<<<136, 256>>>(XH, XP);
    k_topk<<<128, 256>>>(Kp);
    k_deg <<<4, 256>>>();
    k_bn  <<<DD, 256>>>(PB);
    k_out <<<256, 256>>>(PB, G, Be, B, XP, out);
    (void)in_sizes; (void)out_size;
}

// round 5
// speedup vs baseline: 1.9687x; 1.1414x over previous
#include <cuda_runtime.h>
#include <math.h>

#define NN 1024
#define DD 64
#define DPP 32

// ---------------- scratch (device globals) ---------------------------------
__device__ float2   g_d2[NN * NN];        // 8 MB: (dH, dP) pairwise, full mirrored
__device__ unsigned g_mask [NN * 32];     // row-major top-K bitset (fully overwritten)
__device__ unsigned g_maskT[NN * 32];     // transposed bitset (atomicOr; zeroed in k_xy)
__device__ float    g_x[NN * DD];         // XX @ weight
__device__ float    g_y[NN * DD];         // x @ psi_w^T
__device__ int      g_c[NN];              // degree c[j]
__device__ int      g_diag[NN];           // A[j,j]
__device__ unsigned g_mxH, g_mxP;         // float bits (dists >= 0; min is exactly 0)
__device__ float    g_mu[DD], g_istd[DD];
__device__ float    g_bnp[16][2][DD];     // per-block BN partials (s1, s2)

// ---------------- 1. x = XX@W ; y = x@psi_w^T  (+ init of maskT / maxes) ---
__global__ void k_xy(const float* __restrict__ XX, const float* __restrict__ W,
                     const float* __restrict__ PW) {
    // init section (runs before k_dist/k_topk by stream order)
    int gt = blockIdx.x * 256 + threadIdx.x;     // 16384 threads
    g_maskT[gt * 2]     = 0u;
    g_maskT[gt * 2 + 1] = 0u;
    if (gt == 0) { g_mxH = 0u; g_mxP = 0u; }

    __shared__ float sW[64 * 64];     // sW[k*64+d]
    __shared__ float sPW[64 * 65];    // sPW[d*65+k] (padded)
    __shared__ float sXX[16 * 64];
    __shared__ float sx[16 * 64];
    int t = threadIdx.x;
    int row0 = blockIdx.x * 16;

    for (int idx = t; idx < 4096; idx += 256) sW[idx] = W[idx];
    for (int idx = t; idx < 4096; idx += 256) {
        int d = idx >> 6, k = idx & 63;
        sPW[d * 65 + k] = PW[idx];
    }
    for (int idx = t; idx < 1024; idx += 256) sXX[idx] = XX[row0 * 64 + idx];
    __syncthreads();

    int d = t & 63, rg = t >> 6;
    float acc[4] = {0.f, 0.f, 0.f, 0.f};
    #pragma unroll
    for (int k = 0; k < 64; ++k) {
        float wv = sW[k * 64 + d];
        #pragma unroll
        for (int rr = 0; rr < 4; ++rr) acc[rr] += sXX[(rg * 4 + rr) * 64 + k] * wv;
    }
    #pragma unroll
    for (int rr = 0; rr < 4; ++rr) {
        sx[(rg * 4 + rr) * 64 + d] = acc[rr];
        g_x[(row0 + rg * 4 + rr) * 64 + d] = acc[rr];
    }
    __syncthreads();

    float a2[4] = {0.f, 0.f, 0.f, 0.f};
    #pragma unroll
    for (int k = 0; k < 64; ++k) {
        float pw = sPW[d * 65 + k];
        #pragma unroll
        for (int rr = 0; rr < 4; ++rr) a2[rr] += sx[(rg * 4 + rr) * 64 + k] * pw;
    }
    #pragma unroll
    for (int rr = 0; rr < 4; ++rr) g_y[(row0 + rg * 4 + rr) * 64 + d] = a2[rr];
}

// ---------------- 2. distances: 64x64 tiles, 4x4 reg blocking, mirrored ----
__global__ void k_dist(const float* __restrict__ XH, const float* __restrict__ XP) {
    __shared__ float pool[64 * 66 * 2];   // 8448 floats = 33 KB, phase-aliased
    int t = threadIdx.x;

    // decode upper-triangle tile index (136 blocks over 16x16 tiles, by<=bx)
    int by = 0, rem = blockIdx.x;
    while (rem >= 16 - by) { rem -= 16 - by; ++by; }
    int bx = by + rem;
    int i0 = by * 64, j0 = bx * 64;
    int tx = t & 15, ty = t >> 4;
    const float sig = (float)(0.1 + 2.220446049250313e-16);  // sigma + float64 eps

    // phase 1: H features (64 dims)
    float (*sA)[65] = (float(*)[65])pool;
    float (*sB)[65] = (float(*)[65])(pool + 64 * 65);
    for (int idx = t; idx < 4096; idx += 256) {
        int r = idx >> 6, d = idx & 63;
        sA[r][d] = XH[(i0 + r) * 64 + d] / sig;
        sB[r][d] = XH[(j0 + r) * 64 + d] / sig;
    }
    __syncthreads();

    float accH[4][4];
    #pragma unroll
    for (int a = 0; a < 4; ++a)
        #pragma unroll
        for (int b = 0; b < 4; ++b) accH[a][b] = 0.f;
    #pragma unroll 8
    for (int d = 0; d < 64; ++d) {
        float rI[4], rJ[4];
        #pragma unroll
        for (int a = 0; a < 4; ++a) rI[a] = sA[ty + 16 * a][d];
        #pragma unroll
        for (int b = 0; b < 4; ++b) rJ[b] = sB[tx + 16 * b][d];
        #pragma unroll
        for (int a = 0; a < 4; ++a)
            #pragma unroll
            for (int b = 0; b < 4; ++b) {
                float df = rI[a] - rJ[b];
                accH[a][b] += df * df;
            }
    }
    __syncthreads();

    // phase 2: P features (32 dims), reuse pool
    float (*pA)[33] = (float(*)[33])pool;
    float (*pB)[33] = (float(*)[33])(pool + 64 * 33);
    for (int idx = t; idx < 2048; idx += 256) {
        int r = idx >> 5, p = idx & 31;
        pA[r][p] = XP[(i0 + r) * 32 + p];
        pB[r][p] = XP[(j0 + r) * 32 + p];
    }
    __syncthreads();

    float accP[4][4];
    #pragma unroll
    for (int a = 0; a < 4; ++a)
        #pragma unroll
        for (int b = 0; b < 4; ++b) accP[a][b] = 0.f;
    #pragma unroll 8
    for (int p = 0; p < 32; ++p) {
        float rI[4], rJ[4];
        #pragma unroll
        for (int a = 0; a < 4; ++a) rI[a] = pA[ty + 16 * a][p];
        #pragma unroll
        for (int b = 0; b < 4; ++b) rJ[b] = pB[tx + 16 * b][p];
        #pragma unroll
        for (int a = 0; a < 4; ++a)
            #pragma unroll
            for (int b = 0; b < 4; ++b) {
                float df = rI[a] - rJ[b];
                accP[a][b] += df * df;
            }
    }

    // phase 3: sqrt, straight write, max tracking
    float2 res[4][4];
    unsigned lmH = 0u, lmP = 0u;
    #pragma unroll
    for (int a = 0; a < 4; ++a)
        #pragma unroll
        for (int b = 0; b < 4; ++b) {
            float dh = sqrtf(accH[a][b]);
            float dp = sqrtf(accP[a][b]);
            res[a][b] = make_float2(dh, dp);
            lmH = max(lmH, __float_as_uint(dh));
            lmP = max(lmP, __float_as_uint(dp));
            g_d2[(i0 + ty + 16 * a) * NN + (j0 + tx + 16 * b)] = res[a][b];
        }
    lmH = __reduce_max_sync(0xffffffffu, lmH);
    lmP = __reduce_max_sync(0xffffffffu, lmP);
    if ((t & 31) == 0) { atomicMax(&g_mxH, lmH); atomicMax(&g_mxP, lmP); }

    // phase 4: mirror tile via shared transpose (coalesced both ways)
    if (bx != by) {
        __syncthreads();                              // done reading P smem
        float2 (*st)[66] = (float2(*)[66])pool;
        #pragma unroll
        for (int a = 0; a < 4; ++a)
            #pragma unroll
            for (int b = 0; b < 4; ++b)
                st[tx + 16 * b][ty + 16 * a] = res[a][b];
        __syncthreads();
        for (int idx = t; idx < 4096; idx += 256) {
            int r = idx >> 6, c = idx & 63;
            g_d2[(j0 + r) * NN + (i0 + c)] = st[r][c];
        }
    }
}

// ---------------- 3. fused WW + exact top-K (one warp per row) -------------
__global__ void k_topk(const int* __restrict__ Kp) {
    int t = threadIdx.x, lane = t & 31, w = t >> 5;
    int i = blockIdx.x * 8 + w;

    float mxH = __uint_as_float(g_mxH), mxP = __uint_as_float(g_mxP);
    float invH = 0.5f / mxH;              // min is exactly 0 (diagonal)
    float invP = 1.0f / mxP;

    // load row, compute WW keys (WW > 0 -> float bits are uint-ordered)
    unsigned key[32];
    #pragma unroll
    for (int s = 0; s < 32; ++s) {
        float2 dv = g_d2[i * NN + s * 32 + lane];
        float ww = expf(-dv.x * invH) + 0.2f * expf(-dv.y * invP);
        key[s] = __float_as_uint(ww);
    }

    int K = Kp ? Kp[0] : 16;
    if (K < 1) K = 1; if (K > NN) K = NN;

    unsigned mrow = 0u;                   // lane L accumulates mask word L
    for (int it = 0; it < K; ++it) {
        unsigned lm = 0u;
        #pragma unroll
        for (int s = 0; s < 32; ++s) lm = max(lm, key[s]);
        unsigned wm = __reduce_max_sync(0xffffffffu, lm);
        // lowest j holding wm (exact jax tie semantics)
        int jc = 0x7fffffff;
        #pragma unroll
        for (int s = 0; s < 32; ++s)
            if (key[s] == wm && s * 32 + lane < jc) jc = s * 32 + lane;
        int jmin = __reduce_min_sync(0xffffffffu, (unsigned)jc);
        // remove from owner lane; record bit
        if (lane == (jmin & 31)) key[jmin >> 5] = 0u;
        if (lane == (jmin >> 5)) mrow |= 1u << (jmin & 31);
        if (lane == 0)
            atomicOr(&g_maskT[jmin * 32 + (i >> 5)], 1u << (i & 31));
    }
    g_mask[i * 32 + lane] = mrow;
}

// ---------------- 4. degrees + diagonal: one warp per node j ---------------
__global__ void k_deg() {
    int t = threadIdx.x, lane = t & 31, w = t >> 5;
    int j = blockIdx.x * 8 + w;
    unsigned m = g_mask[j * 32 + lane] | g_maskT[j * 32 + lane];
    int c = __reduce_add_sync(0xffffffffu, __popc(m));
    int db = (int)((m >> (j & 31)) & 1u);           // valid on lane == j>>5
    db = __shfl_sync(0xffffffffu, db, j >> 5);
    if (lane == 0) { g_c[j] = c; g_diag[j] = db; }
}

// ---------------- 5a. BN partials: 16 blocks, coalesced row scans ----------
__global__ void k_bn1(const float* __restrict__ psi_b) {
    __shared__ float ss1[4][64], ss2[4][64];
    int t = threadIdx.x, d = t & 63, rg = t >> 6;
    int j0 = blockIdx.x * 64;
    float b = psi_b[d];
    float s1 = 0.f, s2 = 0.f;
    for (int jb = 0; jb < 64; jb += 4) {
        int j = j0 + jb + rg;
        float yv = g_y[j * DD + d];                 // fully coalesced
        float c  = (float)g_c[j];
        s1 += yv * ((float)NN + c);
        float h1 = yv + b, h2 = 2.f * yv + b;
        s2 += ((float)NN - c) * h1 * h1 + c * h2 * h2;
    }
    ss1[rg][d] = s1; ss2[rg][d] = s2;
    __syncthreads();
    if (rg == 0) {
        float a1 = ss1[0][d] + ss1[1][d] + ss1[2][d] + ss1[3][d];
        float a2 = ss2[0][d] + ss2[1][d] + ss2[2][d] + ss2[3][d];
        g_bnp[blockIdx.x][0][d] = a1;
        g_bnp[blockIdx.x][1][d] = a2;
    }
}

// ---------------- 5b. BN finalize (one block, 64 threads) ------------------
__global__ void k_bn2(const float* __restrict__ psi_b) {
    int d = threadIdx.x;
    float s1 = 0.f, s2 = 0.f;
    #pragma unroll
    for (int bl = 0; bl < 16; ++bl) {
        s1 += g_bnp[bl][0][d];
        s2 += g_bnp[bl][1][d];
    }
    const float invN2 = 1.0f / ((float)NN * (float)NN);
    float mu  = psi_b[d] + s1 * invN2;
    float var = s2 * invN2 - mu * mu;
    g_mu[d]   = mu;
    g_istd[d] = rsqrtf(var + 1e-5f);
}

// ---------------- 6. final output (all three out segments) -----------------
__global__ void k_out(const float* __restrict__ psi_b, const float* __restrict__ gamma,
                      const float* __restrict__ beta, const float* __restrict__ bias,
                      const float* __restrict__ XP, float* __restrict__ out) {
    int idx = blockIdx.x * 256 + threadIdx.x;   // 65536 total
    int j = idx >> 6, d = idx & 63;
    float yv = g_y[idx], xv = g_x[idx];
    float z = (2.f * yv + psi_b[d] - g_mu[d]) * g_istd[d] * gamma[d] + beta[d];
    float s = 1.0f / (1.0f + expf(-z));
    float dg = (float)g_diag[j], c = (float)g_c[j];
    float val = xv * (dg + (c - dg) * s) + bias[d];
    out[idx] = val;                               // out[:, :DH] segment
    out[NN * DD + NN * DPP + idx] = val;          // full out segment
    if (idx < NN * DPP) out[NN * DD + idx] = XP[idx];  // XP passthrough
}

// ---------------- launch ----------------------------------------------------
extern "C" void kernel_launch(void* const* d_in, const int* in_sizes, int n_in,
                              void* d_out, int out_size) {
    // expected order: XH, XP, XX, K, weight, bias, psi_w, psi_b, gamma, beta
    int iXH = 0, iXP = 1, iXX = 2, iK = 3, iW = 4, iB = 5, iPW = 6, iPB = 7, iG = 8, iBe = 9;
    if (n_in == 9) {  // K dropped as a scalar
        iK = -1; iW = 3; iB = 4; iPW = 5; iPB = 6; iG = 7; iBe = 8;
    }
    const float* XH  = (const float*)d_in[iXH];
    const float* XP  = (const float*)d_in[iXP];
    const float* XX  = (const float*)d_in[iXX];
    const int*   Kp  = (iK >= 0) ? (const int*)d_in[iK] : nullptr;
    const float* W   = (const float*)d_in[iW];
    const float* B   = (const float*)d_in[iB];
    const float* PW  = (const float*)d_in[iPW];
    const float* PB  = (const float*)d_in[iPB];
    const float* G   = (const float*)d_in[iG];
    const float* Be  = (const float*)d_in[iBe];
    float* out = (float*)d_out;

    k_xy  <<<64, 256>>>(XX, W, PW);       // also zeroes maskT + resets maxes
    k_dist<<<136, 256>>>(XH, XP);
    k_topk<<<128, 256>>>(Kp);
    k_deg <<<128, 256>>>();
    k_bn1 <<<16, 256>>>(PB);
    k_bn2 <<<1, 64>>>(PB);
    k_out <<<256, 256>>>(PB, G, Be, B, XP, out);
    (void)in_sizes; (void)out_size;
}